// round 1
// baseline (speedup 1.0000x reference)
#include <cuda_runtime.h>
#include <math.h>

#define HD   512
#define BD   32
#define SD   2048
#define K2   1024      /* 2H */
#define W4H  2048      /* row length of attn_w = 4H */
#define NEGV (-1e10f)

#define BM   64
#define BK   16
#define BNP  516       /* 512 + pad 4 */

__device__ float g_hb[BD * HD];
__device__ float g_attn[BD * SD];

__device__ __forceinline__ unsigned long long fma2(unsigned long long a,
                                                   unsigned long long b,
                                                   unsigned long long c) {
    unsigned long long d;
    asm("fma.rn.f32x2 %0, %1, %2, %3;" : "=l"(d) : "l"(a), "l"(b), "l"(c));
    return d;
}

// ---------------- kernel 1: g_hb[b][h] = bias[h] + hidden[b,:] . W[h, :1024]
__global__ void hb_kernel(const float* __restrict__ hidden,
                          const float* __restrict__ attn_w,
                          const float* __restrict__ attn_b) {
    int b = blockIdx.x;
    __shared__ float sh[K2];
    for (int i = threadIdx.x; i < K2; i += blockDim.x) sh[i] = hidden[b * K2 + i];
    __syncthreads();
    int warp = threadIdx.x >> 5, lane = threadIdx.x & 31;
    for (int h = warp * 64; h < warp * 64 + 64; h++) {
        const float* w = attn_w + (size_t)h * W4H;
        float s = 0.f;
        for (int k = lane; k < K2; k += 32) s += sh[k] * w[k];
        #pragma unroll
        for (int o = 16; o > 0; o >>= 1) s += __shfl_down_sync(0xffffffffu, s, o);
        if (lane == 0) g_hb[b * HD + h] = s + attn_b[h];
    }
}

// ---------------- kernel 2: E = eo @ W_e^T ; attn[b,s] = sum_h tanh(E+hb)*v ; mask
__global__ __launch_bounds__(512, 1)
void energy_kernel(const float* __restrict__ eo,
                   const float* __restrict__ attn_w,
                   const float* __restrict__ v,
                   const int*  __restrict__ mask) {
    __shared__ union {
        struct { float A[BK][BM]; float Bt[BK][BNP]; } s;
        float red[BM][65];
    } sm;

    const int b   = blockIdx.y;
    const int s0  = blockIdx.x * BM;
    const int tid = threadIdx.x;
    const int tc  = tid & 63;   // n-group
    const int tr  = tid >> 6;   // m-group (0..7)

    unsigned long long acc[8][4];
    #pragma unroll
    for (int r = 0; r < 8; r++)
        #pragma unroll
        for (int c = 0; c < 4; c++) acc[r][c] = 0ull;

    const float* wbase = attn_w + 1024;  // W_e[h][k] = attn_w[h*2048 + 1024 + k]

    const int arow = tid >> 2;          // for A loads (tid < 256)
    const int akq  = (tid & 3) * 4;

    for (int k0 = 0; k0 < K2; k0 += BK) {
        __syncthreads();
        // ---- stage A tile: A[k][m], 64 rows x 16 k
        if (tid < 256) {
            const float4 av = *(const float4*)(eo +
                ((size_t)(s0 + arow) * BD + b) * K2 + k0 + akq);
            sm.s.A[akq + 0][arow] = av.x;
            sm.s.A[akq + 1][arow] = av.y;
            sm.s.A[akq + 2][arow] = av.z;
            sm.s.A[akq + 3][arow] = av.w;
        }
        // ---- stage B tile: Bt[k][n], 512 n x 16 k
        #pragma unroll
        for (int p = 0; p < 4; p++) {
            int idx = p * 512 + tid;
            int n   = idx >> 2;
            int kq  = (idx & 3) * 4;
            const float4 bv = *(const float4*)(wbase + (size_t)n * W4H + k0 + kq);
            sm.s.Bt[kq + 0][n] = bv.x;
            sm.s.Bt[kq + 1][n] = bv.y;
            sm.s.Bt[kq + 2][n] = bv.z;
            sm.s.Bt[kq + 3][n] = bv.w;
        }
        __syncthreads();
        // ---- compute
        #pragma unroll
        for (int k = 0; k < BK; k++) {
            const float* bs = &sm.s.Bt[k][tc * 8];
            const ulonglong2 b01 = *(const ulonglong2*)(bs);
            const ulonglong2 b23 = *(const ulonglong2*)(bs + 4);
            #pragma unroll
            for (int r = 0; r < 8; r++) {
                float a = sm.s.A[k][tr * 8 + r];
                unsigned long long a2;
                asm("mov.b64 %0, {%1, %1};" : "=l"(a2) : "f"(a));
                acc[r][0] = fma2(a2, b01.x, acc[r][0]);
                acc[r][1] = fma2(a2, b01.y, acc[r][1]);
                acc[r][2] = fma2(a2, b23.x, acc[r][2]);
                acc[r][3] = fma2(a2, b23.y, acc[r][3]);
            }
        }
    }

    // ---- epilogue: tanh(E + hb) . v, partial over this thread's 8 n
    float hbv[8], vv[8];
    #pragma unroll
    for (int c = 0; c < 8; c++) {
        int n = tc * 8 + c;
        hbv[c] = g_hb[b * HD + n];
        vv[c]  = v[n];
    }
    float part[8];
    #pragma unroll
    for (int r = 0; r < 8; r++) {
        float sum = 0.f;
        #pragma unroll
        for (int c = 0; c < 4; c++) {
            float lo = __uint_as_float((unsigned)(acc[r][c] & 0xffffffffull));
            float hi = __uint_as_float((unsigned)(acc[r][c] >> 32));
            sum += tanhf(lo + hbv[2 * c])     * vv[2 * c];
            sum += tanhf(hi + hbv[2 * c + 1]) * vv[2 * c + 1];
        }
        part[r] = sum;
    }
    __syncthreads();
    #pragma unroll
    for (int r = 0; r < 8; r++) sm.red[tr * 8 + r][tc] = part[r];
    __syncthreads();
    if (tid < 64) {
        float t = 0.f;
        #pragma unroll 8
        for (int j = 0; j < 64; j++) t += sm.red[tid][j];
        int s  = s0 + tid;
        int mk = mask[b * SD + s];
        g_attn[b * SD + s] = (mk == 0) ? NEGV : t;
    }
}

// ---------------- kernel 3: row softmax over S
__global__ void softmax_kernel(float* __restrict__ out) {
    int b   = blockIdx.x;
    int tid = threadIdx.x;              // 256
    int warp = tid >> 5, lane = tid & 31;
    const float* row = g_attn + b * SD;
    __shared__ float sred[8];

    float vals[8];
    float mx = -INFINITY;
    #pragma unroll
    for (int i = 0; i < 8; i++) {
        vals[i] = row[tid + i * 256];
        mx = fmaxf(mx, vals[i]);
    }
    #pragma unroll
    for (int o = 16; o > 0; o >>= 1) mx = fmaxf(mx, __shfl_xor_sync(0xffffffffu, mx, o));
    if (lane == 0) sred[warp] = mx;
    __syncthreads();
    float bm = sred[0];
    #pragma unroll
    for (int w = 1; w < 8; w++) bm = fmaxf(bm, sred[w]);

    float sum = 0.f;
    #pragma unroll
    for (int i = 0; i < 8; i++) {
        vals[i] = expf(vals[i] - bm);
        sum += vals[i];
    }
    #pragma unroll
    for (int o = 16; o > 0; o >>= 1) sum += __shfl_xor_sync(0xffffffffu, sum, o);
    __syncthreads();
    if (lane == 0) sred[warp] = sum;
    __syncthreads();
    float bs = 0.f;
    #pragma unroll
    for (int w = 0; w < 8; w++) bs += sred[w];
    float inv = 1.f / bs;
    #pragma unroll
    for (int i = 0; i < 8; i++) out[b * SD + tid + i * 256] = vals[i] * inv;
}

extern "C" void kernel_launch(void* const* d_in, const int* in_sizes, int n_in,
                              void* d_out, int out_size) {
    const float* hidden = (const float*)d_in[0];
    const float* eo     = (const float*)d_in[1];
    const int*   mask   = (const int*)  d_in[2];
    const float* attn_w = (const float*)d_in[3];
    const float* attn_b = (const float*)d_in[4];
    const float* v      = (const float*)d_in[5];
    float* out = (float*)d_out;

    hb_kernel<<<BD, 256>>>(hidden, attn_w, attn_b);
    energy_kernel<<<dim3(SD / BM, BD), 512>>>(eo, attn_w, v, mask);
    softmax_kernel<<<BD, 256>>>(out);
}

// round 3
// speedup vs baseline: 2.8835x; 2.8835x over previous
#include <cuda_runtime.h>
#include <cuda_bf16.h>
#include <math.h>
#include <stdint.h>

#define HD   512
#define BD   32
#define SD   2048
#define K2   1024
#define W4H  2048
#define NEGV (-1e10f)

#define TPB    512
#define BM     128
#define BN     256
#define BK     64
#define NCHUNK 16

// smem layout (bytes)
#define BUFSTRIDE 98304          /* 96KB per buffer */
#define OFF_AHI   0              /* 128x64 bf16 = 16KB */
#define OFF_ALO   16384
#define OFF_BHI   32768          /* 256x64 bf16 = 32KB */
#define OFF_BLO   65536
#define OFF_RED   196608         /* 128*4 f32 = 2KB */
#define OFF_V     198656         /* 256 f32 */
#define OFF_HB    0              /* reused: 256*33 f32 = 33.8KB */
#define SMEM_TOTAL 199680

__device__ float g_hb[BD * HD];
__device__ float g_attn0[BD * SD];
__device__ float g_attn1[BD * SD];
__device__ __align__(16) __nv_bfloat16 g_whi[HD * K2];
__device__ __align__(16) __nv_bfloat16 g_wlo[HD * K2];

// ---------------------------------------------------------------- helpers
__device__ __forceinline__ uint32_t smem_u32(const void* p) {
    uint32_t a;
    asm("{ .reg .u64 t; cvta.to.shared.u64 t, %1; cvt.u32.u64 %0, t; }"
        : "=r"(a) : "l"(p));
    return a;
}
__device__ __forceinline__ void cp16(uint32_t dst, const void* src) {
    asm volatile("cp.async.cg.shared.global [%0], [%1], 16;"
                 :: "r"(dst), "l"(src) : "memory");
}
__device__ __forceinline__ void cp_commit() {
    asm volatile("cp.async.commit_group;" ::: "memory");
}
__device__ __forceinline__ void ldmx4(uint32_t* r, uint32_t addr) {
    asm volatile("ldmatrix.sync.aligned.m8n8.x4.shared.b16 {%0,%1,%2,%3}, [%4];"
                 : "=r"(r[0]), "=r"(r[1]), "=r"(r[2]), "=r"(r[3]) : "r"(addr));
}
__device__ __forceinline__ void mma16816(float* c, const uint32_t* a,
                                         uint32_t b0, uint32_t b1) {
    asm("mma.sync.aligned.m16n8k16.row.col.f32.bf16.bf16.f32 "
        "{%0,%1,%2,%3}, {%4,%5,%6,%7}, {%8,%9}, {%0,%1,%2,%3};"
        : "+f"(c[0]), "+f"(c[1]), "+f"(c[2]), "+f"(c[3])
        : "r"(a[0]), "r"(a[1]), "r"(a[2]), "r"(a[3]), "r"(b0), "r"(b1));
}

__device__ __forceinline__ void split4(float4 a, uint2& h, uint2& l) {
    __nv_bfloat16 h0 = __float2bfloat16_rn(a.x);
    __nv_bfloat16 h1 = __float2bfloat16_rn(a.y);
    __nv_bfloat16 h2 = __float2bfloat16_rn(a.z);
    __nv_bfloat16 h3 = __float2bfloat16_rn(a.w);
    __nv_bfloat16 l0 = __float2bfloat16_rn(a.x - __bfloat162float(h0));
    __nv_bfloat16 l1 = __float2bfloat16_rn(a.y - __bfloat162float(h1));
    __nv_bfloat16 l2 = __float2bfloat16_rn(a.z - __bfloat162float(h2));
    __nv_bfloat16 l3 = __float2bfloat16_rn(a.w - __bfloat162float(h3));
    h.x = (uint32_t)__bfloat16_as_ushort(h0) | ((uint32_t)__bfloat16_as_ushort(h1) << 16);
    h.y = (uint32_t)__bfloat16_as_ushort(h2) | ((uint32_t)__bfloat16_as_ushort(h3) << 16);
    l.x = (uint32_t)__bfloat16_as_ushort(l0) | ((uint32_t)__bfloat16_as_ushort(l1) << 16);
    l.y = (uint32_t)__bfloat16_as_ushort(l2) | ((uint32_t)__bfloat16_as_ushort(l3) << 16);
}

// FMA-pipe-only tanh (no MUFU). |err| <= ~2.3e-5.
__device__ __forceinline__ float tanh_fast(float x) {
    float xa = fminf(fmaxf(x, -5.7f), 5.7f);
    float z  = xa * 2.885390081777927f;          // 2x * log2(e)
    float fz = z + 12582912.0f;                  // round-to-nearest int
    int   ni = __float_as_int(fz);
    float f  = z - (fz - 12582912.0f);           // f in [-0.5, 0.5]
    float p  = 1.3333558146e-3f;
    p = fmaf(p, f, 9.6181291076e-3f);
    p = fmaf(p, f, 5.5504108664e-2f);
    p = fmaf(p, f, 2.4022650696e-1f);
    p = fmaf(p, f, 6.9314718056e-1f);
    p = fmaf(p, f, 1.0f);
    float s = __int_as_float((ni << 23) + 0x3F800000); // 2^n
    float t = p * s;                              // e^{2xa}
    float d = t + 1.0f;
    float r = __int_as_float(0x7EF311C3 - __float_as_int(d));
    r = r * (2.0f - d * r);
    r = r * (2.0f - d * r);
    r = r * (2.0f - d * r);
    return (t - 1.0f) * r;
}

// ---------------- prep: split W_e (attn_w[:, 1024:2048]) into bf16 hi/lo
__global__ void prep_w_kernel(const float* __restrict__ attn_w) {
    int n = blockIdx.x;
    int k = threadIdx.x * 4;
    float4 a = *(const float4*)(attn_w + (size_t)n * W4H + 1024 + k);
    uint2 h, l;
    split4(a, h, l);
    *(uint2*)(g_whi + (size_t)n * K2 + k) = h;
    *(uint2*)(g_wlo + (size_t)n * K2 + k) = l;
}

// ---------------- hb: g_hb[b][h] = bias[h] + hidden[b,:] . W[h, :1024]
__global__ void hb_kernel(const float* __restrict__ hidden,
                          const float* __restrict__ attn_w,
                          const float* __restrict__ attn_b) {
    int hc = blockIdx.x, b = blockIdx.y;
    __shared__ float sh[K2];
    for (int i = threadIdx.x; i < K2; i += 256) sh[i] = hidden[b * K2 + i];
    __syncthreads();
    int w = threadIdx.x >> 5, lane = threadIdx.x & 31;
    #pragma unroll
    for (int hi = 0; hi < 8; hi++) {
        int h = hc * 64 + w * 8 + hi;
        const float* wr = attn_w + (size_t)h * W4H;
        float s = 0.f;
        for (int k = lane * 4; k < K2; k += 128) {
            float4 wv = *(const float4*)(wr + k);
            s += sh[k] * wv.x + sh[k + 1] * wv.y + sh[k + 2] * wv.z + sh[k + 3] * wv.w;
        }
        #pragma unroll
        for (int o = 16; o > 0; o >>= 1) s += __shfl_down_sync(0xffffffffu, s, o);
        if (lane == 0) g_hb[b * HD + h] = s + attn_b[h];
    }
}

// ---------------- energy GEMM: mma.sync bf16, 3-term split, fused tanh.v epilogue
__global__ void __launch_bounds__(TPB, 1)
energy_kernel(const float* __restrict__ eo, const float* __restrict__ v) {
    extern __shared__ char smem[];
    const uint32_t sb = smem_u32(smem);
    const int tid  = threadIdx.x;
    const int lane = tid & 31;
    const int warp = tid >> 5;
    const int wm   = warp >> 2;      // 0..3
    const int wn   = warp & 3;       // 0..3

    const int mtile = blockIdx.x >> 1;
    const int nhalf = blockIdx.x & 1;
    const int m0 = mtile * BM;
    const int n0 = nhalf * BN;

    // ldmatrix lane geometry
    const int a_row = wm * 32 + (lane & 7) + ((lane >> 3) & 1) * 8;
    const int a_ku  = (lane >> 4);
    const int b_row = wn * 64 + (lane & 7) + ((lane >> 4) << 3);
    const int b_ku  = (lane >> 3) & 1;
    const int xs    = lane & 7;      // swizzle xor (row & 7)

    float acc[2][8][4];
    #pragma unroll
    for (int mf = 0; mf < 2; mf++)
        #pragma unroll
        for (int nf = 0; nf < 8; nf++)
            #pragma unroll
            for (int i = 0; i < 4; i++) acc[mf][nf][i] = 0.f;

    // -------- chunk loader
    auto issue_chunk = [&](int kc, int buf) {
        const uint32_t bs = sb + buf * BUFSTRIDE;
        // B hi/lo via cp.async (16B units)
        #pragma unroll
        for (int j = 0; j < 4; j++) {
            int idx = tid + j * TPB;           // 0..2047
            int row = idx >> 3, u = idx & 7;
            uint32_t doff = (uint32_t)(row * 128 + ((u ^ (row & 7)) << 4));
            const __nv_bfloat16* sh = g_whi + (size_t)(n0 + row) * K2 + kc + u * 8;
            const __nv_bfloat16* sl = g_wlo + (size_t)(n0 + row) * K2 + kc + u * 8;
            cp16(bs + OFF_BHI + doff, sh);
            cp16(bs + OFF_BLO + doff, sl);
        }
        // A: LDG fp32 -> split -> STS bf16 hi/lo
        #pragma unroll
        for (int j = 0; j < 4; j++) {
            int idx = tid + j * TPB;           // 0..2047
            int row = idx >> 4, q = idx & 15;
            float4 a = *(const float4*)(eo + (size_t)(m0 + row) * K2 + kc + q * 4);
            uint2 h, l;
            split4(a, h, l);
            int u = q >> 1;
            uint32_t doff = (uint32_t)(row * 128 + ((u ^ (row & 7)) << 4) + (q & 1) * 8);
            *(uint2*)(smem + buf * BUFSTRIDE + OFF_AHI + doff) = h;
            *(uint2*)(smem + buf * BUFSTRIDE + OFF_ALO + doff) = l;
        }
        cp_commit();
    };

    issue_chunk(0, 0);
    issue_chunk(BK, 1);

    for (int c = 0; c < NCHUNK; c++) {
        if (c < NCHUNK - 1) asm volatile("cp.async.wait_group 1;" ::: "memory");
        else                asm volatile("cp.async.wait_group 0;" ::: "memory");
        __syncthreads();

        const int buf = c & 1;
        const uint32_t bs = sb + buf * BUFSTRIDE;
        #pragma unroll
        for (int ks = 0; ks < 4; ks++) {
            uint32_t ah[2][4], al[2][4];
            #pragma unroll
            for (int mf = 0; mf < 2; mf++) {
                uint32_t roff = (uint32_t)((a_row + mf * 16) * 128);
                uint32_t uoff = (uint32_t)(((ks * 2 + a_ku) ^ xs) << 4);
                ldmx4(ah[mf], bs + OFF_AHI + roff + uoff);
                ldmx4(al[mf], bs + OFF_ALO + roff + uoff);
            }
            #pragma unroll
            for (int bp = 0; bp < 4; bp++) {
                uint32_t roff = (uint32_t)((b_row + bp * 16) * 128);
                uint32_t uoff = (uint32_t)(((ks * 2 + b_ku) ^ xs) << 4);
                uint32_t bh[4], bl[4];
                ldmx4(bh, bs + OFF_BHI + roff + uoff);
                #pragma unroll
                for (int mf = 0; mf < 2; mf++) {
                    mma16816(acc[mf][bp * 2],     ah[mf], bh[0], bh[1]);
                    mma16816(acc[mf][bp * 2 + 1], ah[mf], bh[2], bh[3]);
                    mma16816(acc[mf][bp * 2],     al[mf], bh[0], bh[1]);
                    mma16816(acc[mf][bp * 2 + 1], al[mf], bh[2], bh[3]);
                }
                ldmx4(bl, bs + OFF_BLO + roff + uoff);
                #pragma unroll
                for (int mf = 0; mf < 2; mf++) {
                    mma16816(acc[mf][bp * 2],     ah[mf], bl[0], bl[1]);
                    mma16816(acc[mf][bp * 2 + 1], ah[mf], bl[2], bl[3]);
                }
            }
        }
        __syncthreads();
        if (c + 2 < NCHUNK) issue_chunk((c + 2) * BK, buf);
    }

    // -------- epilogue: tanh(E + hb) . v
    __syncthreads();
    float* hb_s = (float*)(smem + OFF_HB);     // [256][33]
    float* v_s  = (float*)(smem + OFF_V);      // [256]
    float* red  = (float*)(smem + OFF_RED);    // [128][4]
    for (int i = tid; i < BN * BD; i += TPB) {
        int n = i >> 5, b = i & 31;
        hb_s[n * 33 + b] = g_hb[b * HD + n0 + n];
    }
    for (int i = tid; i < BN; i += TPB) v_s[i] = v[n0 + i];
    __syncthreads();

    const int quad = lane >> 2, qlane = lane & 3;
    #pragma unroll
    for (int mf = 0; mf < 2; mf++) {
        #pragma unroll
        for (int rh = 0; rh < 2; rh++) {
            int m_loc = wm * 32 + mf * 16 + rh * 8 + quad;
            int b = m_loc & 31;
            float p = 0.f;
            #pragma unroll
            for (int nf = 0; nf < 8; nf++) {
                int nl = wn * 64 + nf * 8 + qlane * 2;
                float e0 = acc[mf][nf][rh * 2]     + hb_s[nl * 33 + b];
                float e1 = acc[mf][nf][rh * 2 + 1] + hb_s[(nl + 1) * 33 + b];
                p = fmaf(tanh_fast(e0), v_s[nl],     p);
                p = fmaf(tanh_fast(e1), v_s[nl + 1], p);
            }
            p += __shfl_xor_sync(0xffffffffu, p, 1);
            p += __shfl_xor_sync(0xffffffffu, p, 2);
            if (qlane == 0) red[m_loc * 4 + wn] = p;
        }
    }
    __syncthreads();
    if (tid < BM) {
        int m = m0 + tid;
        float lg = red[tid * 4] + red[tid * 4 + 1] + red[tid * 4 + 2] + red[tid * 4 + 3];
        int s = m >> 5, b = m & 31;
        float* dst = nhalf ? g_attn1 : g_attn0;
        dst[b * SD + s] = lg;
    }
}

// ---------------- softmax over S per batch row (sums the two N-half partials)
__global__ void softmax_kernel(const int* __restrict__ mask, float* __restrict__ out) {
    int b = blockIdx.x;
    int tid = threadIdx.x;             // 256
    int warp = tid >> 5, lane = tid & 31;
    __shared__ float sred[8];

    float vals[8];
    float mx = -INFINITY;
    #pragma unroll
    for (int i = 0; i < 8; i++) {
        int s = tid + i * 256;
        float raw = g_attn0[b * SD + s] + g_attn1[b * SD + s];
        vals[i] = mask[b * SD + s] ? raw : NEGV;
        mx = fmaxf(mx, vals[i]);
    }
    #pragma unroll
    for (int o = 16; o > 0; o >>= 1) mx = fmaxf(mx, __shfl_xor_sync(0xffffffffu, mx, o));
    if (lane == 0) sred[warp] = mx;
    __syncthreads();
    float bm = sred[0];
    #pragma unroll
    for (int w = 1; w < 8; w++) bm = fmaxf(bm, sred[w]);

    float sum = 0.f;
    #pragma unroll
    for (int i = 0; i < 8; i++) {
        vals[i] = expf(vals[i] - bm);
        sum += vals[i];
    }
    #pragma unroll
    for (int o = 16; o > 0; o >>= 1) sum += __shfl_xor_sync(0xffffffffu, sum, o);
    __syncthreads();
    if (lane == 0) sred[warp] = sum;
    __syncthreads();
    float bs = 0.f;
    #pragma unroll
    for (int w = 0; w < 8; w++) bs += sred[w];
    float inv = 1.f / bs;
    #pragma unroll
    for (int i = 0; i < 8; i++) out[b * SD + tid + i * 256] = vals[i] * inv;
}

extern "C" void kernel_launch(void* const* d_in, const int* in_sizes, int n_in,
                              void* d_out, int out_size) {
    const float* hidden = (const float*)d_in[0];
    const float* eo     = (const float*)d_in[1];
    const int*   mask   = (const int*)  d_in[2];
    const float* attn_w = (const float*)d_in[3];
    const float* attn_b = (const float*)d_in[4];
    const float* v      = (const float*)d_in[5];
    float* out = (float*)d_out;

    cudaFuncSetAttribute(energy_kernel,
                         cudaFuncAttributeMaxDynamicSharedMemorySize, SMEM_TOTAL);

    prep_w_kernel<<<HD, 256>>>(attn_w);
    hb_kernel<<<dim3(8, BD), 256>>>(hidden, attn_w, attn_b);
    energy_kernel<<<(SD * BD / BM) * 2, TPB, SMEM_TOTAL>>>(eo, v);
    softmax_kernel<<<BD, 256>>>(mask, out);
}